// round 15
// baseline (speedup 1.0000x reference)
#include <cuda_runtime.h>
#include <cuda_fp16.h>
#include <cstdint>

#define NB 64
#define NN 512
#define ND 128

// pre-normalized features (scaled x16), fp16
__device__ uint4 g_hi[(NB * NN * ND * 2) / 16];

__device__ __forceinline__ uint32_t smem_u32(const void* p) {
    uint32_t a;
    asm("{ .reg .u64 t; cvta.to.shared.u64 t, %1; cvt.u32.u64 %0, t; }" : "=r"(a) : "l"(p));
    return a;
}
__device__ __forceinline__ float fsqrt_approx(float x) {
    float r;
    asm("sqrt.approx.f32 %0, %1;" : "=f"(r) : "f"(x));
    return r;
}

#define LDSM_X4(r, addr)                                                                  \
    asm volatile("ldmatrix.sync.aligned.m8n8.x4.shared.b16 {%0,%1,%2,%3}, [%4];"          \
                 : "=r"((r)[0]), "=r"((r)[1]), "=r"((r)[2]), "=r"((r)[3]) : "r"(addr))

#define CP_ASYNC16(sa, gp)                                                                \
    asm volatile("cp.async.cg.shared.global [%0], [%1], 16;" :: "r"(sa), "l"(gp) : "memory")
#define CP_COMMIT() asm volatile("cp.async.commit_group;" ::: "memory")
#define CP_WAIT(n)  asm volatile("cp.async.wait_group %0;" :: "n"(n) : "memory")

__device__ __forceinline__ void mma16816(float* c, uint32_t a0, uint32_t a1, uint32_t a2,
                                         uint32_t a3, uint32_t b0, uint32_t b1) {
    asm volatile("mma.sync.aligned.m16n8k16.row.col.f32.f16.f16.f32 "
                 "{%0,%1,%2,%3}, {%4,%5,%6,%7}, {%8,%9}, {%0,%1,%2,%3};"
                 : "+f"(c[0]), "+f"(c[1]), "+f"(c[2]), "+f"(c[3])
                 : "r"(a0), "r"(a1), "r"(a2), "r"(a3), "r"(b0), "r"(b1));
}

// ---- smem layout (bytes): 64x64 jobs ----
#define OFF_CI 0              // 64 float2 = 512
#define OFF_CJ 512            // 64 float2 = 512
#define OFF_BUF 1024
#define SMA32 80              // operand row stride (conflict-free ldmatrix)
#define BOFF0  5120           // B plane offset within chunk (64*80)
#define CHUNK  10240          // A(64 rows) + B(64 rows)
// staging overlaps the chunk buffers (valid after the loop's trailing sync)
#define OFF_AVS 1024          // 64 x 72 floats = 18432
#define AVS_S 72
#define OFF_AVT 19456         // 64 x 68 floats = 17408
#define AVT_S 68
#define OFF_SVS 36864         // 64 x 64 bytes = 4096
#define OFF_SVT 40960         // 64 x 64 bytes = 4096
#define SMEM_TOTAL 45056
#define DOT_SCALE 0.00390625f // 1/256 compensates the x16 feature pre-scale

// ---------- prep: normalize rows, scale x16, to fp16 ----------
__global__ void prep_kernel(const float* __restrict__ fea) {
    int row  = blockIdx.x * 8 + (threadIdx.x >> 5);
    int lane = threadIdx.x & 31;
    float4 v = reinterpret_cast<const float4*>(fea + (size_t)row * ND)[lane];
    float s = v.x * v.x + v.y * v.y + v.z * v.z + v.w * v.w;
    #pragma unroll
    for (int o = 16; o > 0; o >>= 1) s += __shfl_xor_sync(0xffffffffu, s, o);
    float rn = 16.0f / fmaxf(sqrtf(s), 1e-8f);
    __half h0 = __float2half_rn(v.x * rn), h1 = __float2half_rn(v.y * rn);
    __half h2 = __float2half_rn(v.z * rn), h3 = __float2half_rn(v.w * rn);
    uint2 hv;
    hv.x = (uint32_t)__half_as_ushort(h0) | ((uint32_t)__half_as_ushort(h1) << 16);
    hv.y = (uint32_t)__half_as_ushort(h2) | ((uint32_t)__half_as_ushort(h3) << 16);
    reinterpret_cast<uint2*>(g_hi)[(size_t)row * 32 + lane] = hv;
}

// issue one K32 chunk: A 256 + B 256 uint4 = 2/thread
__device__ __forceinline__ void issue_chunk(uint32_t bufBase, int tid, int b,
                                            int iBase, int jBase, int kc) {
    #pragma unroll
    for (int it = 0; it < 2; it++) {
        int idx = tid + it * 256;
        int row, c8, grow;
        uint32_t soff;
        if (idx < 256) {                   // A rows
            row = idx >> 2;
            c8 = (idx & 3) * 8;
            grow = iBase + row;
            soff = (uint32_t)(row * SMA32 + c8 * 2);
        } else {                           // B rows
            int e = idx - 256;
            row = e >> 2;
            c8 = (e & 3) * 8;
            grow = jBase + row;
            soff = (uint32_t)(BOFF0 + row * SMA32 + c8 * 2);
        }
        const uint4* gp = &g_hi[((size_t)(b * NN + grow) * ND + kc * 32 + c8) >> 3];
        CP_ASYNC16(bufBase + soff, gp);
    }
    CP_COMMIT();
}

// ---------- main: 64x64 jobs, 256 threads, 4 CTAs/SM ----------
__global__ __launch_bounds__(256, 4)
void adj_mma_kernel(const float* __restrict__ coord, float* __restrict__ out) {
    extern __shared__ char sm[];
    const uint32_t smb = smem_u32(sm);
    const int tid  = threadIdx.x;
    const int wid  = tid >> 5;
    const int lane = tid & 31;
    const int wy = wid & 1;           // 0..1, m dim (32 rows)
    const int wx = wid >> 1;          // 0..3, n dim (16 cols)

    const int blk = blockIdx.x;
    const int b = blk / 36;
    const int t = blk % 36;
    const unsigned char bi_t[36] = {0,0,0,0,0,0,0,0, 1,1,1,1,1,1,1, 2,2,2,2,2,2,
                                    3,3,3,3,3, 4,4,4,4, 5,5,5, 6,6, 7};
    const unsigned char bj_t[36] = {0,1,2,3,4,5,6,7, 1,2,3,4,5,6,7, 2,3,4,5,6,7,
                                    3,4,5,6,7, 4,5,6,7, 5,6,7, 6,7, 7};
    const int iBase = bi_t[t] * 64;
    const int jBase = bj_t[t] * 64;
    const bool diag = (iBase == jBase);

    // prologue: chunks 0,1 in flight
    issue_chunk(smb + OFF_BUF,         tid, b, iBase, jBase, 0);
    issue_chunk(smb + OFF_BUF + CHUNK, tid, b, iBase, jBase, 1);

    // stage coords while loads stream
    {
        float2* ci2 = reinterpret_cast<float2*>(sm + OFF_CI);
        float2* cj2 = reinterpret_cast<float2*>(sm + OFF_CJ);
        if (tid < 64)
            ci2[tid] = reinterpret_cast<const float2*>(coord)[(size_t)b * NN + iBase + tid];
        else if (tid < 128)
            cj2[tid - 64] = reinterpret_cast<const float2*>(coord)[(size_t)b * NN + jBase + (tid - 64)];
    }

    float acc[2][2][4];
    #pragma unroll
    for (int mt = 0; mt < 2; mt++)
        #pragma unroll
        for (int nt = 0; nt < 2; nt++)
            #pragma unroll
            for (int q = 0; q < 4; q++) acc[mt][nt][q] = 0.0f;

    const uint32_t aOff = (uint32_t)(OFF_BUF + (wy * 32 + lane) * SMA32);
    // folded B: lanes 0-15 -> rows @k0-7, lanes 16-31 -> same rows @k8-15
    const uint32_t bOff = (uint32_t)(OFF_BUF + BOFF0 + (wx * 16 + (lane & 15)) * SMA32 + (lane >> 4) * 16);

    #pragma unroll
    for (int kc = 0; kc < 4; kc++) {
        if (kc < 3) CP_WAIT(1); else CP_WAIT(0);
        __syncthreads();

        const uint32_t bsel = (uint32_t)((kc & 1) * CHUNK);
        const uint32_t aH = smb + aOff + bsel;
        const uint32_t bH = smb + bOff + bsel;

        #pragma unroll
        for (int ks = 0; ks < 2; ks++) {
            const uint32_t co = (uint32_t)(ks * 32);
            uint32_t ah1[4], ah2[4], bh[4];
            LDSM_X4(ah1, aH + co);
            LDSM_X4(ah2, aH + co + 16);
            LDSM_X4(bh, bH + co);      // bh[nt] = n-grp nt k0-7, bh[nt+2] = k8-15
            #pragma unroll
            for (int mt = 0; mt < 2; mt++)
                #pragma unroll
                for (int nt = 0; nt < 2; nt++)
                    mma16816(acc[mt][nt], ah1[mt*2], ah1[mt*2+1], ah2[mt*2], ah2[mt*2+1],
                             bh[nt], bh[nt+2]);
        }

        __syncthreads();
        if (kc < 2) issue_chunk(smb + OFF_BUF + bsel, tid, b, iBase, jBase, kc + 2);
    }

    // staging: av (row-major + transposed) and sv as bytes; no gmem traffic
    {
        const float2* ci2 = reinterpret_cast<const float2*>(sm + OFF_CI);
        const float2* cj2 = reinterpret_cast<const float2*>(sm + OFF_CJ);
        float* avs = reinterpret_cast<float*>(sm + OFF_AVS);
        float* avt = reinterpret_cast<float*>(sm + OFF_AVT);
        unsigned char* svs = reinterpret_cast<unsigned char*>(sm + OFF_SVS);
        unsigned char* svt = reinterpret_cast<unsigned char*>(sm + OFF_SVT);
        const int g = lane >> 2, q = lane & 3;

        #pragma unroll
        for (int mt = 0; mt < 2; mt++) {
            #pragma unroll
            for (int nt = 0; nt < 2; nt++) {
                const float* c = acc[mt][nt];
                const int lj = wx * 16 + nt * 8 + q * 2;       // 0..63
                const float2 cj0 = cj2[lj], cj1 = cj2[lj + 1];
                #pragma unroll
                for (int h = 0; h < 2; h++) {
                    const int li = wy * 32 + mt * 16 + g + h * 8;   // 0..63
                    const float2 ci = ci2[li];
                    float dx0 = ci.x - cj0.x, dy0 = ci.y - cj0.y;
                    float dx1 = ci.x - cj1.x, dy1 = ci.y - cj1.y;
                    float d20 = dx0 * dx0 + dy0 * dy0;
                    float d21 = dx1 * dx1 + dy1 * dy1;
                    bool s0 = diag && (li == lj);
                    bool s1 = diag && (li == lj + 1);
                    float av0 = s0 ? 0.0f : c[h * 2 + 0] * (__expf(-fsqrt_approx(d20)) * DOT_SCALE);
                    float av1 = s1 ? 0.0f : c[h * 2 + 1] * (__expf(-fsqrt_approx(d21)) * DOT_SCALE);
                    unsigned char b0 = (!s0 && d20 < 1.0f) ? 1 : 0;
                    unsigned char b1 = (!s1 && d21 < 1.0f) ? 1 : 0;
                    *reinterpret_cast<float2*>(avs + (size_t)li * AVS_S + lj) = make_float2(av0, av1);
                    svs[li * 64 + lj]     = b0;
                    svs[li * 64 + lj + 1] = b1;
                    if (!diag) {
                        avt[(size_t)lj * AVT_S + li]       = av0;
                        avt[(size_t)(lj + 1) * AVT_S + li] = av1;
                        svt[lj * 64 + li]       = b0;
                        svt[(lj + 1) * 64 + li] = b1;
                    }
                }
            }
        }
    }
    __syncthreads();

    // coalesced write pass: pure float4 stores, sv from staged bytes
    {
        const float* avs = reinterpret_cast<const float*>(sm + OFF_AVS);
        const float* avt = reinterpret_cast<const float*>(sm + OFF_AVT);
        float* outA = out;
        float* outS = out + (size_t)NB * NN * NN;
        const size_t base = (size_t)b * NN * NN;

        // direct: 64 rows x 64 cols = 1024 float4 -> 4/thread
        {
            int row0 = tid >> 4;            // 0..15
            int c4 = (tid & 15) * 4;        // 0..60
            size_t ro = base + (size_t)(iBase + row0) * NN + jBase + c4;
            const float* ap = avs + (size_t)row0 * AVS_S + c4;
            const unsigned char* sp = reinterpret_cast<const unsigned char*>(sm + OFF_SVS) + row0 * 64 + c4;
            #pragma unroll
            for (int it = 0; it < 4; it++) {
                float4 av4 = *reinterpret_cast<const float4*>(ap);
                uint32_t w = *reinterpret_cast<const uint32_t*>(sp);
                float4 sv4;
                sv4.x = (w & 0x000000ffu) ? 1.0f : 0.0f;
                sv4.y = (w & 0x0000ff00u) ? 1.0f : 0.0f;
                sv4.z = (w & 0x00ff0000u) ? 1.0f : 0.0f;
                sv4.w = (w & 0xff000000u) ? 1.0f : 0.0f;
                *reinterpret_cast<float4*>(outA + ro) = av4;
                *reinterpret_cast<float4*>(outS + ro) = sv4;
                ro += (size_t)16 * NN;
                ap += 16 * AVS_S;
                sp += 16 * 64;
            }
        }
        // mirror
        if (!diag) {
            int row0 = tid >> 4;
            int c4 = (tid & 15) * 4;
            size_t ro = base + (size_t)(jBase + row0) * NN + iBase + c4;
            const float* ap = avt + (size_t)row0 * AVT_S + c4;
            const unsigned char* sp = reinterpret_cast<const unsigned char*>(sm + OFF_SVT) + row0 * 64 + c4;
            #pragma unroll
            for (int it = 0; it < 4; it++) {
                float4 av4 = *reinterpret_cast<const float4*>(ap);
                uint32_t w = *reinterpret_cast<const uint32_t*>(sp);
                float4 sv4;
                sv4.x = (w & 0x000000ffu) ? 1.0f : 0.0f;
                sv4.y = (w & 0x0000ff00u) ? 1.0f : 0.0f;
                sv4.z = (w & 0x00ff0000u) ? 1.0f : 0.0f;
                sv4.w = (w & 0xff000000u) ? 1.0f : 0.0f;
                *reinterpret_cast<float4*>(outA + ro) = av4;
                *reinterpret_cast<float4*>(outS + ro) = sv4;
                ro += (size_t)16 * NN;
                ap += 16 * AVT_S;
                sp += 16 * 64;
            }
        }
    }
}

extern "C" void kernel_launch(void* const* d_in, const int* in_sizes, int n_in,
                              void* d_out, int out_size) {
    (void)in_sizes; (void)n_in; (void)out_size;
    const float* fea   = (const float*)d_in[0];
    const float* coord = (const float*)d_in[1];
    float* out = (float*)d_out;

    prep_kernel<<<NB * NN / 8, 256>>>(fea);

    cudaFuncSetAttribute(adj_mma_kernel, cudaFuncAttributeMaxDynamicSharedMemorySize, SMEM_TOTAL);
    adj_mma_kernel<<<NB * 36, 256, SMEM_TOTAL>>>(coord, out);
}

// round 16
// speedup vs baseline: 1.0970x; 1.0970x over previous
#include <cuda_runtime.h>
#include <cuda_fp16.h>
#include <cstdint>

#define NB 64
#define NN 512
#define ND 128

// pre-normalized features (scaled x16), fp16
__device__ uint4 g_hi[(NB * NN * ND * 2) / 16];

__device__ __forceinline__ uint32_t smem_u32(const void* p) {
    uint32_t a;
    asm("{ .reg .u64 t; cvta.to.shared.u64 t, %1; cvt.u32.u64 %0, t; }" : "=r"(a) : "l"(p));
    return a;
}
__device__ __forceinline__ float fsqrt_approx(float x) {
    float r;
    asm("sqrt.approx.f32 %0, %1;" : "=f"(r) : "f"(x));
    return r;
}

#define LDSM_X4(r, addr)                                                                  \
    asm volatile("ldmatrix.sync.aligned.m8n8.x4.shared.b16 {%0,%1,%2,%3}, [%4];"          \
                 : "=r"((r)[0]), "=r"((r)[1]), "=r"((r)[2]), "=r"((r)[3]) : "r"(addr))

#define CP_ASYNC16(sa, gp)                                                                \
    asm volatile("cp.async.cg.shared.global [%0], [%1], 16;" :: "r"(sa), "l"(gp) : "memory")
#define CP_COMMIT() asm volatile("cp.async.commit_group;" ::: "memory")
#define CP_WAIT(n)  asm volatile("cp.async.wait_group %0;" :: "n"(n) : "memory")

__device__ __forceinline__ void mma16816(float* c, uint32_t a0, uint32_t a1, uint32_t a2,
                                         uint32_t a3, uint32_t b0, uint32_t b1) {
    asm volatile("mma.sync.aligned.m16n8k16.row.col.f32.f16.f16.f32 "
                 "{%0,%1,%2,%3}, {%4,%5,%6,%7}, {%8,%9}, {%0,%1,%2,%3};"
                 : "+f"(c[0]), "+f"(c[1]), "+f"(c[2]), "+f"(c[3])
                 : "r"(a0), "r"(a1), "r"(a2), "r"(a3), "r"(b0), "r"(b1));
}

// ---- smem layout (bytes): 128x64 jobs ----
#define OFF_CI 0              // 128 float2 = 1024
#define OFF_CJ 1024           // 64 float2 = 512
#define OFF_BUF 1536
#define SMA32 80              // operand row stride (conflict-free ldmatrix)
#define BOFF0  10240          // B plane offset within chunk (128*80)
#define CHUNK  15360          // A(128 rows) + B(64 rows); 4 buffers -> [1536, 62976)
// staging (valid after final mainloop sync, overlaps buffers):
// avs row = 64 av floats + 16 pad floats, sv bytes live in the pad [256..320)
#define OFF_AVS 1536          // 128 rows x 320 B = 40960 -> [1536, 42496)
#define AVS_S 80              // floats
#define SV_BYTE_OFF 256       // byte offset of sv bytes within an avs row
#define OFF_AVT 42496         // 64 x 132 floats = 33792 -> [42496, 76288)
#define AVT_S 132
#define SMEM_TOTAL 76288
#define DOT_SCALE 0.00390625f // 1/256 compensates the x16 feature pre-scale

// ---------- prep: normalize rows, scale x16, to fp16 ----------
__global__ void prep_kernel(const float* __restrict__ fea) {
    int row  = blockIdx.x * 8 + (threadIdx.x >> 5);
    int lane = threadIdx.x & 31;
    float4 v = reinterpret_cast<const float4*>(fea + (size_t)row * ND)[lane];
    float s = v.x * v.x + v.y * v.y + v.z * v.z + v.w * v.w;
    #pragma unroll
    for (int o = 16; o > 0; o >>= 1) s += __shfl_xor_sync(0xffffffffu, s, o);
    float rn = 16.0f / fmaxf(sqrtf(s), 1e-8f);
    __half h0 = __float2half_rn(v.x * rn), h1 = __float2half_rn(v.y * rn);
    __half h2 = __float2half_rn(v.z * rn), h3 = __float2half_rn(v.w * rn);
    uint2 hv;
    hv.x = (uint32_t)__half_as_ushort(h0) | ((uint32_t)__half_as_ushort(h1) << 16);
    hv.y = (uint32_t)__half_as_ushort(h2) | ((uint32_t)__half_as_ushort(h3) << 16);
    reinterpret_cast<uint2*>(g_hi)[(size_t)row * 32 + lane] = hv;
}

// issue one K32 chunk: A 512 + B 256 uint4 = 3/thread
__device__ __forceinline__ void issue_chunk(uint32_t bufBase, int tid, int b,
                                            int iBase, int jBase64, int kc) {
    #pragma unroll
    for (int it = 0; it < 3; it++) {
        int idx = tid + it * 256;
        int row, c8, grow;
        uint32_t soff;
        if (idx < 512) {                   // A rows
            row = idx >> 2;
            c8 = (idx & 3) * 8;
            grow = iBase + row;
            soff = (uint32_t)(row * SMA32 + c8 * 2);
        } else {                           // B rows
            int e = idx - 512;
            row = e >> 2;
            c8 = (e & 3) * 8;
            grow = jBase64 + row;
            soff = (uint32_t)(BOFF0 + row * SMA32 + c8 * 2);
        }
        const uint4* gp = &g_hi[((size_t)(b * NN + grow) * ND + kc * 32 + c8) >> 3];
        CP_ASYNC16(bufBase + soff, gp);
    }
    CP_COMMIT();
}

// ---------- main: 128x64 half-tile jobs, 256 threads, 3 CTAs/SM ----------
__global__ __launch_bounds__(256, 3)
void adj_mma_kernel(const float* __restrict__ coord, float* __restrict__ out) {
    extern __shared__ char sm[];
    const uint32_t smb = smem_u32(sm);
    const int tid  = threadIdx.x;
    const int wid  = tid >> 5;
    const int lane = tid & 31;
    const int wy = wid & 3;           // 0..3, m dim (32 rows each)
    const int wx = wid >> 2;          // 0..1, n dim (32 cols each)

    const int blk = blockIdx.x;
    const int b = blk / 20;
    const int rem = blk % 20;
    const int t = rem >> 1;
    const int jHalf = rem & 1;
    const unsigned char bi_t[10] = {0,0,0,0,1,1,1,2,2,3};
    const unsigned char bj_t[10] = {0,1,2,3,1,2,3,2,3,3};
    const int iBase = bi_t[t] * 128;
    const int jBase = bj_t[t] * 128;
    const int jBase64 = jBase + jHalf * 64;
    const bool diag = (iBase == jBase);

    // prologue: all 4 chunks in flight (4 commit groups, distinct buffers)
    issue_chunk(smb + OFF_BUF + 0 * CHUNK, tid, b, iBase, jBase64, 0);
    issue_chunk(smb + OFF_BUF + 1 * CHUNK, tid, b, iBase, jBase64, 1);
    issue_chunk(smb + OFF_BUF + 2 * CHUNK, tid, b, iBase, jBase64, 2);
    issue_chunk(smb + OFF_BUF + 3 * CHUNK, tid, b, iBase, jBase64, 3);

    // stage coords while loads stream
    {
        float2* ci2 = reinterpret_cast<float2*>(sm + OFF_CI);
        float2* cj2 = reinterpret_cast<float2*>(sm + OFF_CJ);
        if (tid < 128)
            ci2[tid] = reinterpret_cast<const float2*>(coord)[(size_t)b * NN + iBase + tid];
        else if (tid < 192)
            cj2[tid - 128] = reinterpret_cast<const float2*>(coord)[(size_t)b * NN + jBase64 + (tid - 128)];
    }

    float acc[2][4][4];
    #pragma unroll
    for (int mt = 0; mt < 2; mt++)
        #pragma unroll
        for (int nt = 0; nt < 4; nt++)
            #pragma unroll
            for (int q = 0; q < 4; q++) acc[mt][nt][q] = 0.0f;

    const uint32_t aOff = (uint32_t)(OFF_BUF + (wy * 32 + lane) * SMA32);
    const uint32_t bOff = (uint32_t)(OFF_BUF + BOFF0 + (wx * 32 + lane) * SMA32);

    #pragma unroll
    for (int kc = 0; kc < 4; kc++) {
        if (kc == 0) CP_WAIT(3);
        else if (kc == 1) CP_WAIT(2);
        else if (kc == 2) CP_WAIT(1);
        else CP_WAIT(0);
        __syncthreads();

        const uint32_t bsel = (uint32_t)(kc * CHUNK);
        const uint32_t aH = smb + aOff + bsel;
        const uint32_t bH = smb + bOff + bsel;

        #pragma unroll
        for (int ks = 0; ks < 2; ks++) {
            const uint32_t co = (uint32_t)(ks * 32);
            uint32_t ah1[4], ah2[4], bh1[4], bh2[4];
            LDSM_X4(ah1, aH + co);
            LDSM_X4(ah2, aH + co + 16);
            LDSM_X4(bh1, bH + co);
            LDSM_X4(bh2, bH + co + 16);
            #pragma unroll
            for (int mt = 0; mt < 2; mt++)
                #pragma unroll
                for (int nt = 0; nt < 4; nt++)
                    mma16816(acc[mt][nt], ah1[mt*2], ah1[mt*2+1], ah2[mt*2], ah2[mt*2+1],
                             bh1[nt], bh2[nt]);
        }
    }
    __syncthreads();   // all warps done with buffers; staging overlaps them

    // staging: av (row-major + transposed) and direct-tile sv bytes in avs pad
    {
        const float2* ci2 = reinterpret_cast<const float2*>(sm + OFF_CI);
        const float2* cj2 = reinterpret_cast<const float2*>(sm + OFF_CJ);
        float* avs = reinterpret_cast<float*>(sm + OFF_AVS);
        float* avt = reinterpret_cast<float*>(sm + OFF_AVT);
        const int g = lane >> 2, q = lane & 3;

        #pragma unroll
        for (int mt = 0; mt < 2; mt++) {
            #pragma unroll
            for (int nt = 0; nt < 4; nt++) {
                const float* c = acc[mt][nt];
                const int lj = wx * 32 + nt * 8 + q * 2;       // 0..63
                const float2 cj0 = cj2[lj], cj1 = cj2[lj + 1];
                #pragma unroll
                for (int h = 0; h < 2; h++) {
                    const int li = wy * 32 + mt * 16 + g + h * 8;   // 0..127
                    const float2 ci = ci2[li];
                    float dx0 = ci.x - cj0.x, dy0 = ci.y - cj0.y;
                    float dx1 = ci.x - cj1.x, dy1 = ci.y - cj1.y;
                    float d20 = dx0 * dx0 + dy0 * dy0;
                    float d21 = dx1 * dx1 + dy1 * dy1;
                    bool s0 = diag && (li == jHalf * 64 + lj);
                    bool s1 = diag && (li == jHalf * 64 + lj + 1);
                    float av0 = s0 ? 0.0f : c[h * 2 + 0] * (__expf(-fsqrt_approx(d20)) * DOT_SCALE);
                    float av1 = s1 ? 0.0f : c[h * 2 + 1] * (__expf(-fsqrt_approx(d21)) * DOT_SCALE);
                    unsigned int b0 = (!s0 && d20 < 1.0f) ? 1u : 0u;
                    unsigned int b1 = (!s1 && d21 < 1.0f) ? 1u : 0u;
                    *reinterpret_cast<float2*>(avs + (size_t)li * AVS_S + lj) = make_float2(av0, av1);
                    *reinterpret_cast<unsigned short*>(
                        sm + OFF_AVS + li * (AVS_S * 4) + SV_BYTE_OFF + lj) =
                        (unsigned short)(b0 | (b1 << 8));
                    if (!diag) {
                        avt[(size_t)lj * AVT_S + li]       = av0;
                        avt[(size_t)(lj + 1) * AVT_S + li] = av1;
                    }
                }
            }
        }
    }
    __syncthreads();

    // write pass
    {
        const float* avs = reinterpret_cast<const float*>(sm + OFF_AVS);
        const float* avt = reinterpret_cast<const float*>(sm + OFF_AVT);
        const float2* cj2 = reinterpret_cast<const float2*>(sm + OFF_CJ);
        const float4* ci4 = reinterpret_cast<const float4*>(sm + OFF_CI);
        float* outA = out;
        float* outS = out + (size_t)NB * NN * NN;
        const size_t base = (size_t)b * NN * NN;

        // direct: 128 rows x 64 cols — pure data movement, sv from staged bytes
        #pragma unroll
        for (int it = 0; it < 8; it++) {
            int idx = tid + it * 256;
            int row = idx >> 4;            // 0..127
            int c4 = (idx & 15) * 4;       // 0..60
            float4 av4 = *reinterpret_cast<const float4*>(avs + (size_t)row * AVS_S + c4);
            uint32_t w = *reinterpret_cast<const uint32_t*>(
                sm + OFF_AVS + row * (AVS_S * 4) + SV_BYTE_OFF + c4);
            float4 sv4;
            sv4.x = (w & 0x000000ffu) ? 1.0f : 0.0f;
            sv4.y = (w & 0x0000ff00u) ? 1.0f : 0.0f;
            sv4.z = (w & 0x00ff0000u) ? 1.0f : 0.0f;
            sv4.w = (w & 0xff000000u) ? 1.0f : 0.0f;
            size_t ro = base + (size_t)(iBase + row) * NN + jBase64 + c4;
            *reinterpret_cast<float4*>(outA + ro) = av4;
            *reinterpret_cast<float4*>(outS + ro) = sv4;
        }

        // mirror: 64 rows x 128 cols — sv recomputed from coords (off-diag only)
        if (!diag) {
            #pragma unroll
            for (int it = 0; it < 8; it++) {
                int idx = tid + it * 256;
                int row = idx >> 5;        // 0..63
                int c4 = (idx & 31) * 4;   // 0..124
                float4 av4 = *reinterpret_cast<const float4*>(avt + (size_t)row * AVT_S + c4);
                float2 cj = cj2[row];
                float4 p0 = ci4[c4 >> 1], p1 = ci4[(c4 >> 1) + 1];
                float d0x = cj.x - p0.x, d0y = cj.y - p0.y;
                float d1x = cj.x - p0.z, d1y = cj.y - p0.w;
                float d2x = cj.x - p1.x, d2y = cj.y - p1.y;
                float d3x = cj.x - p1.z, d3y = cj.y - p1.w;
                float4 sv4;
                sv4.x = (d0x * d0x + d0y * d0y < 1.0f) ? 1.0f : 0.0f;
                sv4.y = (d1x * d1x + d1y * d1y < 1.0f) ? 1.0f : 0.0f;
                sv4.z = (d2x * d2x + d2y * d2y < 1.0f) ? 1.0f : 0.0f;
                sv4.w = (d3x * d3x + d3y * d3y < 1.0f) ? 1.0f : 0.0f;
                size_t ro = base + (size_t)(jBase64 + row) * NN + iBase + c4;
                *reinterpret_cast<float4*>(outA + ro) = av4;
                *reinterpret_cast<float4*>(outS + ro) = sv4;
            }
        }
    }
}

extern "C" void kernel_launch(void* const* d_in, const int* in_sizes, int n_in,
                              void* d_out, int out_size) {
    (void)in_sizes; (void)n_in; (void)out_size;
    const float* fea   = (const float*)d_in[0];
    const float* coord = (const float*)d_in[1];
    float* out = (float*)d_out;

    prep_kernel<<<NB * NN / 8, 256>>>(fea);

    cudaFuncSetAttribute(adj_mma_kernel, cudaFuncAttributeMaxDynamicSharedMemorySize, SMEM_TOTAL);
    adj_mma_kernel<<<NB * 20, 256, SMEM_TOTAL>>>(coord, out);
}